// round 9
// baseline (speedup 1.0000x reference)
#include <cuda_runtime.h>
#include <cuda_bf16.h>
#include <cstdint>

// SumPooling / segment_sum with SORTED index (int32 or int64 — auto-detected).
// x: [N, 128] f32, index: [N] sorted, out: [16384, 128] f32.
//
// K1: one coalesced pass over index -> g_start[s] = lower_bound(index, s).
// K2: ONE WARP PER SEGMENT. Lane l owns feature columns [4l, 4l+4) (32 lanes
//     x float4 = 128 cols exactly). The warp streams its segment's contiguous
//     rows with a 4-deep unroll (4 independent loads in flight), then does a
//     single coalesced float4 store. No smem, no syncthreads, no atomics,
//     no epilogue bubbles -> DRAM stays saturated.

#define D_FEAT      128
#define N_SEGMENTS  16384
#define WARPS       8

__device__ int g_start[N_SEGMENTS + 1];

// JAX with x64 disabled silently downgrades int64 -> int32. Probe: read the
// middle of the buffer as int64. True int64 -> small value in [0,16384).
// int32 -> aliases two packed sorted int32s near the end -> huge.
__device__ __forceinline__ bool idx_is64(const void* __restrict__ idx, int n)
{
    long long probe = __ldg((const long long*)idx + ((n >> 1) - 1));
    return (probe >= 0 && probe < N_SEGMENTS);
}

template <bool IS64>
__device__ __forceinline__ int load_seg(const void* __restrict__ idx, int i)
{
    if (IS64) return (int)__ldg((const long long*)idx + i);
    else      return __ldg((const int*)idx + i);
}

template <bool IS64>
__device__ __forceinline__ void boundaries_body(const void* __restrict__ index, int n)
{
    int i = blockIdx.x * blockDim.x + threadIdx.x;
    if (i >= n) return;

    int curr = load_seg<IS64>(index, i);
    int prev = (i == 0) ? -1 : load_seg<IS64>(index, i - 1);

    // start[s] = i for all s in (prev, curr]
    for (int s = prev + 1; s <= curr; ++s) g_start[s] = i;

    if (i == n - 1) {
        for (int s = curr + 1; s <= N_SEGMENTS; ++s) g_start[s] = n;
    }
}

__global__ __launch_bounds__(256)
void seg_boundaries_kernel(const void* __restrict__ index, int n)
{
    if (idx_is64(index, n)) boundaries_body<true >(index, n);
    else                    boundaries_body<false>(index, n);
}

__global__ __launch_bounds__(WARPS * 32)
void segsum_kernel(const float* __restrict__ x, float* __restrict__ out)
{
    const int seg  = blockIdx.x * WARPS + (threadIdx.x >> 5);
    const int lane = threadIdx.x & 31;

    const int s0 = g_start[seg];
    const int s1 = g_start[seg + 1];

    const float4* __restrict__ x4 = reinterpret_cast<const float4*>(x);

    float4 a0 = make_float4(0.f, 0.f, 0.f, 0.f);
    float4 a1 = make_float4(0.f, 0.f, 0.f, 0.f);
    float4 a2 = make_float4(0.f, 0.f, 0.f, 0.f);
    float4 a3 = make_float4(0.f, 0.f, 0.f, 0.f);

    int r = s0;
    // 4 independent loads in flight per warp.
    for (; r + 4 <= s1; r += 4) {
        float4 v0 = __ldg(x4 + (long long)(r + 0) * 32 + lane);
        float4 v1 = __ldg(x4 + (long long)(r + 1) * 32 + lane);
        float4 v2 = __ldg(x4 + (long long)(r + 2) * 32 + lane);
        float4 v3 = __ldg(x4 + (long long)(r + 3) * 32 + lane);
        a0.x += v0.x; a0.y += v0.y; a0.z += v0.z; a0.w += v0.w;
        a1.x += v1.x; a1.y += v1.y; a1.z += v1.z; a1.w += v1.w;
        a2.x += v2.x; a2.y += v2.y; a2.z += v2.z; a2.w += v2.w;
        a3.x += v3.x; a3.y += v3.y; a3.z += v3.z; a3.w += v3.w;
    }
    for (; r < s1; ++r) {
        float4 v = __ldg(x4 + (long long)r * 32 + lane);
        a0.x += v.x; a0.y += v.y; a0.z += v.z; a0.w += v.w;
    }

    a0.x += a1.x + a2.x + a3.x;
    a0.y += a1.y + a2.y + a3.y;
    a0.z += a1.z + a2.z + a3.z;
    a0.w += a1.w + a2.w + a3.w;

    // Single coalesced 512B store per warp (zeros for empty segments).
    reinterpret_cast<float4*>(out)[(long long)seg * 32 + lane] = a0;
}

extern "C" void kernel_launch(void* const* d_in, const int* in_sizes, int n_in,
                              void* d_out, int out_size)
{
    const float* x     = (const float*)d_in[0];
    const void*  index = d_in[1];
    float*       out   = (float*)d_out;

    const int n_rows = in_sizes[0] / D_FEAT;   // 1,000,000

    seg_boundaries_kernel<<<(n_rows + 255) / 256, 256>>>(index, n_rows);
    segsum_kernel<<<N_SEGMENTS / WARPS, WARPS * 32>>>(x, out);
}

// round 10
// speedup vs baseline: 1.0438x; 1.0438x over previous
#include <cuda_runtime.h>
#include <cuda_bf16.h>
#include <cstdint>

// SumPooling / segment_sum with SORTED index (int32 or int64 — auto-detected).
// x: [N, 128] f32, index: [N] sorted, out: [16384, 128] f32.
//
// K1: vectorized pass over index (4 elements/thread) -> g_start[s] =
//     lower_bound(index, s). Empty segments handled; tail filled to n.
// K2: one CTA per segment (PROVEN best @ 79.5us, 82.9% DRAM): 8 warps stream
//     the segment's contiguous rows (float4 per lane, 2-deep MLP), smem
//     cross-warp reduce, single coalesced store (zeros for empty segments).

#define D_FEAT      128
#define N_SEGMENTS  16384

__device__ int g_start[N_SEGMENTS + 1];

// JAX with x64 disabled silently downgrades int64 -> int32. Probe: read the
// middle of the buffer as int64. True int64 -> small value in [0,16384).
// int32 -> aliases two packed sorted int32s near the end -> huge.
__device__ __forceinline__ bool idx_is64(const void* __restrict__ idx, int n)
{
    long long probe = __ldg((const long long*)idx + ((n >> 1) - 1));
    return (probe >= 0 && probe < N_SEGMENTS);
}

// ---------------- K1: boundaries (4 elements per thread) ----------------

template <bool IS64>
__device__ __forceinline__ void boundaries_body(const void* __restrict__ index, int n)
{
    const int t    = blockIdx.x * blockDim.x + threadIdx.x;
    const int base = t * 4;
    if (base >= n) return;

    int v[4];
    int cnt = (n - base >= 4) ? 4 : (n - base);

    if (IS64) {
        const long long* p = (const long long*)index;
        if (cnt == 4) {
            longlong2 lo = __ldg((const longlong2*)(p + base));
            longlong2 hi = __ldg((const longlong2*)(p + base) + 1);
            v[0] = (int)lo.x; v[1] = (int)lo.y; v[2] = (int)hi.x; v[3] = (int)hi.y;
        } else {
            for (int k = 0; k < cnt; ++k) v[k] = (int)__ldg(p + base + k);
        }
    } else {
        const int* p = (const int*)index;
        if (cnt == 4) {
            int4 q = __ldg((const int4*)(p + base));
            v[0] = q.x; v[1] = q.y; v[2] = q.z; v[3] = q.w;
        } else {
            for (int k = 0; k < cnt; ++k) v[k] = __ldg(p + base + k);
        }
    }

    int prev;
    if (base == 0) prev = -1;
    else prev = IS64 ? (int)__ldg((const long long*)index + base - 1)
                     : __ldg((const int*)index + base - 1);

    #pragma unroll
    for (int k = 0; k < 4; ++k) {
        if (k < cnt) {
            // start[s] = base+k for all s in (prev, v[k]]
            for (int s = prev + 1; s <= v[k]; ++s) g_start[s] = base + k;
            prev = v[k];
        }
    }

    if (base + cnt == n) {
        for (int s = prev + 1; s <= N_SEGMENTS; ++s) g_start[s] = n;
    }
}

__global__ __launch_bounds__(256)
void seg_boundaries_kernel(const void* __restrict__ index, int n)
{
    if (idx_is64(index, n)) boundaries_body<true >(index, n);
    else                    boundaries_body<false>(index, n);
}

// ---------------- K2: CTA per segment (R8 proven design) ----------------

#define WARPS 8

__global__ __launch_bounds__(WARPS * 32)
void segsum_kernel(const float* __restrict__ x, float* __restrict__ out)
{
    __shared__ float4 red[WARPS][32];

    const int seg  = blockIdx.x;
    const int w    = threadIdx.x >> 5;
    const int lane = threadIdx.x & 31;

    const int s0 = g_start[seg];
    const int s1 = g_start[seg + 1];

    const float4* __restrict__ x4 = reinterpret_cast<const float4*>(x);

    float4 a0 = make_float4(0.f, 0.f, 0.f, 0.f);
    float4 a1 = make_float4(0.f, 0.f, 0.f, 0.f);

    int r = s0 + w;
    for (; r + WARPS < s1; r += 2 * WARPS) {
        float4 v0 = __ldg(x4 + (long long)r * 32 + lane);
        float4 v1 = __ldg(x4 + (long long)(r + WARPS) * 32 + lane);
        a0.x += v0.x; a0.y += v0.y; a0.z += v0.z; a0.w += v0.w;
        a1.x += v1.x; a1.y += v1.y; a1.z += v1.z; a1.w += v1.w;
    }
    if (r < s1) {
        float4 v0 = __ldg(x4 + (long long)r * 32 + lane);
        a0.x += v0.x; a0.y += v0.y; a0.z += v0.z; a0.w += v0.w;
    }
    a0.x += a1.x; a0.y += a1.y; a0.z += a1.z; a0.w += a1.w;

    red[w][lane] = a0;
    __syncthreads();

    if (threadIdx.x < 128) {
        const int t = threadIdx.x;
        float4 s = red[0][t & 31];
        #pragma unroll
        for (int ww = 1; ww < WARPS; ++ww) {
            float4 v = red[ww][t & 31];
            s.x += v.x; s.y += v.y; s.z += v.z; s.w += v.w;
        }
        float val = (t >> 5) == 0 ? s.x : (t >> 5) == 1 ? s.y : (t >> 5) == 2 ? s.z : s.w;
        out[(long long)seg * D_FEAT + 4 * (t & 31) + (t >> 5)] = val;
    }
}

extern "C" void kernel_launch(void* const* d_in, const int* in_sizes, int n_in,
                              void* d_out, int out_size)
{
    const float* x     = (const float*)d_in[0];
    const void*  index = d_in[1];
    float*       out   = (float*)d_out;

    const int n_rows = in_sizes[0] / D_FEAT;   // 1,000,000

    const int k1_threads = (n_rows + 3) / 4;
    seg_boundaries_kernel<<<(k1_threads + 255) / 256, 256>>>(index, n_rows);
    segsum_kernel<<<N_SEGMENTS, WARPS * 32>>>(x, out);
}